// round 5
// baseline (speedup 1.0000x reference)
#include <cuda_runtime.h>
#include <cuda_bf16.h>

// Problem shape (fixed by reference setup_inputs)
#define B 64
#define T 4096
#define H 512

// Scratch (no allocation allowed in kernel_launch)
__device__ float g_v[B * H];        // v = hidden @ W   [B, H]
__device__ float g_scores[B * T];   // raw scores       [B, T]

// ---------------------------------------------------------------------------
// Kernel 1: v[b,h] = sum_o hidden[b,o] * W[o,h]
// Grid: (H/32, B/4) = 256 blocks x 1024 threads = 32 h-lanes x 32 o-groups,
// BTILE=4 batches per thread. 55 warps/SM (~86% occ) hides L2 latency on the
// coalesced W column walk; each W load feeds 4 FMAs, W L2 traffic = 16MB.
// Cross-og reduction through smem.
// ---------------------------------------------------------------------------
__global__ void __launch_bounds__(1024, 1)
proj_hidden_kernel(const float* __restrict__ hidden,
                   const float* __restrict__ W) {
    const int b0 = blockIdx.y * 4;
    const int h0 = blockIdx.x * 32;
    const int hl = threadIdx.x & 31;     // h lane
    const int og = threadIdx.x >> 5;     // o-group 0..31 (warp-uniform)

    __shared__ float sh[4][H];
    // stage 4 hidden rows: 2048 floats / 1024 threads -> float2 each
    {
        const int r = threadIdx.x >> 8;          // 0..3
        const int c = threadIdx.x & 255;         // 0..255 float2 slots
        reinterpret_cast<float2*>(sh[r])[c] =
            reinterpret_cast<const float2*>(hidden + (size_t)(b0 + r) * H)[c];
    }
    __syncthreads();

    const float* __restrict__ wp = W + (size_t)(og * 16) * H + h0 + hl;
    const int ob = og * 16;
    float acc0 = 0.0f, acc1 = 0.0f, acc2 = 0.0f, acc3 = 0.0f;
#pragma unroll
    for (int o = 0; o < 16; ++o) {
        const float w = wp[(size_t)o * H];
        acc0 += sh[0][ob + o] * w;
        acc1 += sh[1][ob + o] * w;
        acc2 += sh[2][ob + o] * w;
        acc3 += sh[3][ob + o] * w;
    }

    __shared__ float part[32][4][32];
    part[og][0][hl] = acc0;
    part[og][1][hl] = acc1;
    part[og][2][hl] = acc2;
    part[og][3][hl] = acc3;
    __syncthreads();
    if (threadIdx.x < 128) {
        const int bb = threadIdx.x >> 5;   // 0..3
        const int hh = threadIdx.x & 31;
        float r = 0.0f;
#pragma unroll
        for (int g = 0; g < 32; ++g) r += part[g][bb][hh];
        g_v[(size_t)(b0 + bb) * H + h0 + hh] = r;
    }
}

// ---------------------------------------------------------------------------
// Kernel 2: scores[b,t] = enc[b,t,:] . v[b,:]
// Grid: (T/64, B). 256 threads = 8 warps; each warp owns 8 consecutive t.
// __ldcs on enc: single-use 512MB stream, evict-first so L2 keeps W/v/scores.
// ---------------------------------------------------------------------------
__global__ void scores_kernel(const float* __restrict__ enc) {
    const int b    = blockIdx.y;
    const int tile = blockIdx.x;          // 64 t-values per block
    const int tid  = threadIdx.x;         // 256
    const int warp = tid >> 5;
    const int lane = tid & 31;

    __shared__ float sv[H];
    reinterpret_cast<float2*>(sv)[tid] =
        reinterpret_cast<const float2*>(g_v + b * H)[tid];
    __syncthreads();

    const float4* __restrict__ vb = reinterpret_cast<const float4*>(sv);
    const float4* __restrict__ base =
        reinterpret_cast<const float4*>(enc + (size_t)b * T * H);

#pragma unroll
    for (int i = 0; i < 8; ++i) {
        const int t = tile * 64 + warp * 8 + i;
        const float4* __restrict__ row = base + (size_t)t * (H / 4);

        float acc = 0.0f;
#pragma unroll
        for (int k = 0; k < 4; ++k) {
            const float4 x = __ldcs(row + lane + k * 32);
            const float4 w = vb[lane + k * 32];
            acc += x.x * w.x + x.y * w.y + x.z * w.z + x.w * w.w;
        }
#pragma unroll
        for (int off = 16; off; off >>= 1)
            acc += __shfl_xor_sync(0xffffffffu, acc, off);
        if (lane == 0) g_scores[b * T + t] = acc;
    }
}

// ---------------------------------------------------------------------------
// Kernel 3: row softmax over T. One block per b, 1024 threads, float4/thread.
// ---------------------------------------------------------------------------
__global__ void softmax_kernel(float* __restrict__ out) {
    const int b   = blockIdx.x;
    const int tid = threadIdx.x;          // 1024
    const int warp = tid >> 5;
    const int lane = tid & 31;

    const float4 x = reinterpret_cast<const float4*>(g_scores + b * T)[tid];

    __shared__ float red[32];
    __shared__ float sbc;

    // --- block max ---
    float m = fmaxf(fmaxf(x.x, x.y), fmaxf(x.z, x.w));
#pragma unroll
    for (int off = 16; off; off >>= 1)
        m = fmaxf(m, __shfl_xor_sync(0xffffffffu, m, off));
    if (lane == 0) red[warp] = m;
    __syncthreads();
    if (tid < 32) {
        float mm = red[tid];
#pragma unroll
        for (int off = 16; off; off >>= 1)
            mm = fmaxf(mm, __shfl_xor_sync(0xffffffffu, mm, off));
        if (tid == 0) sbc = mm;
    }
    __syncthreads();
    m = sbc;

    // --- exp + block sum ---
    const float e0 = expf(x.x - m);
    const float e1 = expf(x.y - m);
    const float e2 = expf(x.z - m);
    const float e3 = expf(x.w - m);
    float s = (e0 + e1) + (e2 + e3);
#pragma unroll
    for (int off = 16; off; off >>= 1)
        s += __shfl_xor_sync(0xffffffffu, s, off);
    __syncthreads();   // protect red[] reuse
    if (lane == 0) red[warp] = s;
    __syncthreads();
    if (tid < 32) {
        float ss = red[tid];
#pragma unroll
        for (int off = 16; off; off >>= 1)
            ss += __shfl_xor_sync(0xffffffffu, ss, off);
        if (tid == 0) sbc = ss;
    }
    __syncthreads();
    const float inv = 1.0f / sbc;

    float4 y;
    y.x = e0 * inv; y.y = e1 * inv; y.z = e2 * inv; y.w = e3 * inv;
    reinterpret_cast<float4*>(out + b * T)[tid] = y;
}

// ---------------------------------------------------------------------------
extern "C" void kernel_launch(void* const* d_in, const int* in_sizes, int n_in,
                              void* d_out, int out_size) {
    const float* hidden = (const float*)d_in[0];   // [B, H]
    const float* enc    = (const float*)d_in[1];   // [B, T, H]
    const float* W      = (const float*)d_in[2];   // [H, H]
    // d_in[3] = bias: cancels under softmax, unused.
    float* out = (float*)d_out;                    // [B, 1, T]

    {
        dim3 grid(H / 32, B / 4);
        proj_hidden_kernel<<<grid, 1024>>>(hidden, W);
    }
    {
        dim3 grid(T / 64, B);
        scores_kernel<<<grid, 256>>>(enc);
    }
    softmax_kernel<<<B, 1024>>>(out);
}